// round 14
// baseline (speedup 1.0000x reference)
#include <cuda_runtime.h>
#include <cuda_fp16.h>
#include <math.h>
#include <stdint.h>

// ---------------------------------------------------------------------------
// Problem constants
// ---------------------------------------------------------------------------
constexpr int SEQ    = 2048;
constexpr int DIM    = 2048;
constexpr int NH     = 16;
constexpr int QR     = 1536;
constexpr int KVR    = 512;
constexpr int ROPE_D = 64;
constexpr int NOPE   = 128;
constexpr int VDIM   = 128;
constexpr int QKD    = NOPE + ROPE_D;          // 192
constexpr int KVUP_D = NOPE + VDIM;            // 256
constexpr float EPSF = 1e-6f;
constexpr int  NSM_SLOTS = 296;                // 148 SMs x 2 CTAs

// ---------------------------------------------------------------------------
// Scratch (device globals: allocation-free) — all-half intermediates
// ---------------------------------------------------------------------------
__device__ __align__(256) __half g_cqh  [SEQ * QR];
__device__ __align__(256) __half g_kvh  [SEQ * (KVR + ROPE_D)];
__device__ __align__(256) __half g_ckvh [SEQ * KVR];
__device__ __align__(256) __half g_qh   [SEQ * NH * QKD];      // scaled + roped
__device__ __align__(256) __half g_kropeh[SEQ * ROPE_D];
__device__ __align__(256) __half g_kvuph[SEQ * NH * KVUP_D];   // k_nope | v
__device__ __align__(256) __half g_attnh[SEQ * NH * VDIM];
__device__ __align__(256) float  g_cos  [SEQ * (ROPE_D / 2)];
__device__ __align__(256) float  g_sin  [SEQ * (ROPE_D / 2)];
// half operand copies
__device__ __align__(256) __half g_xh   [SEQ * DIM];
__device__ __align__(256) __half g_wqkvdh[(QR + KVR + ROPE_D) * DIM];
__device__ __align__(256) __half g_wquh [NH * QKD * QR];       // pre-scaled
__device__ __align__(256) __half g_wkvuh[NH * KVUP_D * KVR];
__device__ __align__(256) __half g_woh  [DIM * NH * VDIM];

// ---------------------------------------------------------------------------
// helpers
// ---------------------------------------------------------------------------
__device__ __forceinline__ uint32_t packh2(float a, float b) {
    __half2 h = __floats2half2_rn(a, b);
    return *reinterpret_cast<uint32_t*>(&h);
}

#define MMA_F16(D0,D1,D2,D3,A0,A1,A2,A3,B0,B1)                               \
    asm volatile(                                                            \
        "mma.sync.aligned.m16n8k16.row.col.f32.f16.f16.f32 "                 \
        "{%0,%1,%2,%3},{%4,%5,%6,%7},{%8,%9},{%0,%1,%2,%3};"                 \
        : "+f"(D0), "+f"(D1), "+f"(D2), "+f"(D3)                             \
        : "r"(A0), "r"(A1), "r"(A2), "r"(A3), "r"(B0), "r"(B1))

#define LDSM_X4(R0,R1,R2,R3,ADDR)                                            \
    asm volatile(                                                            \
        "ldmatrix.sync.aligned.m8n8.x4.shared.b16 {%0,%1,%2,%3}, [%4];"      \
        : "=r"(R0), "=r"(R1), "=r"(R2), "=r"(R3) : "r"(ADDR))

#define LDSM_X4_T(R0,R1,R2,R3,ADDR)                                          \
    asm volatile(                                                            \
        "ldmatrix.sync.aligned.m8n8.x4.trans.shared.b16 {%0,%1,%2,%3}, [%4];"\
        : "=r"(R0), "=r"(R1), "=r"(R2), "=r"(R3) : "r"(ADDR))

#define CP_ASYNC16(DST,SRC)                                                  \
    asm volatile("cp.async.cg.shared.global [%0], [%1], 16;"                 \
                 :: "r"(DST), "l"(SRC))

// 16-byte half vector (8 halves)
struct __align__(16) h8 { __half2 h[4]; };

// ---------------------------------------------------------------------------
// float -> half conversion (reads 2 float4 = 8 floats, writes one h8)
// ---------------------------------------------------------------------------
__global__ void __launch_bounds__(256) f2h_kernel(
    const float4* __restrict__ src, h8* __restrict__ dst, int n8, float scale)
{
    for (int i = blockIdx.x * 256 + threadIdx.x; i < n8; i += gridDim.x * 256) {
        const float4 v0 = src[2 * i];
        const float4 v1 = src[2 * i + 1];
        h8 o;
        o.h[0] = __floats2half2_rn(v0.x * scale, v0.y * scale);
        o.h[1] = __floats2half2_rn(v0.z * scale, v0.w * scale);
        o.h[2] = __floats2half2_rn(v1.x * scale, v1.y * scale);
        o.h[3] = __floats2half2_rn(v1.z * scale, v1.w * scale);
        dst[i] = o;
    }
}

// ---------------------------------------------------------------------------
// Persistent fp16 NT GEMM: C[M,N] = A[M,K](f16) * B[N,K](f16)^T
// 128x128 tiles, 8 warps x (64x32), m16n8k16, ldmatrix, 3-stage cp.async.
// Each CTA loops over tiles (linear scheduler) — no wave quantization.
// HALF_OUT: write __half. SPLIT: cols [0,N1)->C, [N1,N)->C2.
// ROPEQ: fused RoPE on columns with (col % 192) >= 128 (rows = tokens).
// ---------------------------------------------------------------------------
constexpr int GBM = 128, GBN = 128, GBKH = 64, HSTR = 72;
constexpr int GTILE_H = (GBM + GBN) * HSTR;
constexpr int GSTAGES = 3;
constexpr int GEMM_SMEM = GSTAGES * GTILE_H * 2;
constexpr int A_OFF_B  = GBM * HSTR * 2;

template<bool SPLIT, bool HALF_OUT, bool ROPEQ>
__global__ void __launch_bounds__(256, 2) gemm_f16_kernel(
    const __half* __restrict__ A, const __half* __restrict__ B,
    void* __restrict__ C, void* __restrict__ C2,
    int M, int N, int N1, int N2, int K)
{
    extern __shared__ __half smh[];

    const int tid  = threadIdx.x;
    const int warp = tid >> 5;
    const int lane = tid & 31;
    const int g    = lane >> 2;
    const int tg   = lane & 3;
    const int wm   = (warp & 1) * 64;
    const int wn   = (warp >> 1) * 32;

    const uint32_t s0 = (uint32_t)__cvta_generic_to_shared(smh);
    const int nk     = K / GBKH;
    const int gridX  = (N + GBN - 1) / GBN;
    const int ntiles = gridX * (M / GBM);

    // ldmatrix per-lane offsets (tile-invariant)
    const int aRow = lane & 15;
    const int aK8  = (lane >> 4) * 8;
    uint32_t aOff[4];
#pragma unroll
    for (int mt = 0; mt < 4; mt++)
        aOff[mt] = ((wm + mt * 16 + aRow) * HSTR + aK8) * 2;
    const int bRowL = (lane & 7) + ((lane & 16) ? 8 : 0);
    const int bK8   = lane & 8;
    uint32_t bOff[2];
#pragma unroll
    for (int p = 0; p < 2; p++)
        bOff[p] = ((wn + p * 16 + bRowL) * HSTR + bK8) * 2 + A_OFF_B;

    for (int tile = blockIdx.x; tile < ntiles; tile += gridDim.x) {
        const int bm0 = (tile / gridX) * GBM;
        const int bn0 = (tile % gridX) * GBN;

        auto load_tiles = [&](int slot, int k0) {
            const uint32_t sA = s0 + slot * (GTILE_H * 2);
            const uint32_t sB = sA + A_OFF_B;
#pragma unroll
            for (int i = 0; i < 4; i++) {
                const int c   = tid + i * 256;
                const int row = c >> 3;
                const int seg = c & 7;
                const uint32_t da = sA + (row * HSTR + seg * 8) * 2;
                const __half* ga = A + (size_t)(bm0 + row) * K + k0 + seg * 8;
                CP_ASYNC16(da, ga);
            }
#pragma unroll
            for (int i = 0; i < 4; i++) {
                const int c   = tid + i * 256;
                const int row = c >> 3;
                const int seg = c & 7;
                const int rb  = bn0 + row;
                const int ok  = (rb < N) ? 16 : 0;
                const __half* gb = B + (size_t)(ok ? rb : 0) * K + k0 + seg * 8;
                const uint32_t db = sB + (row * HSTR + seg * 8) * 2;
                asm volatile("cp.async.cg.shared.global [%0], [%1], 16, %2;"
                             :: "r"(db), "l"(gb), "r"(ok));
            }
        };

        float acc[4][4][4];
#pragma unroll
        for (int mt = 0; mt < 4; mt++)
#pragma unroll
            for (int nt = 0; nt < 4; nt++)
#pragma unroll
                for (int v = 0; v < 4; v++) acc[mt][nt][v] = 0.f;

#pragma unroll
        for (int s = 0; s < GSTAGES - 1; s++) {
            if (s < nk) load_tiles(s, s * GBKH);
            asm volatile("cp.async.commit_group;");
        }

        for (int kt = 0; kt < nk; kt++) {
            asm volatile("cp.async.wait_group %0;" :: "n"(GSTAGES - 2));
            __syncthreads();

            if (kt + GSTAGES - 1 < nk)
                load_tiles((kt + GSTAGES - 1) % GSTAGES,
                           (kt + GSTAGES - 1) * GBKH);
            asm volatile("cp.async.commit_group;");

            const uint32_t sbase = s0 + (kt % GSTAGES) * (GTILE_H * 2);

#pragma unroll
            for (int s16 = 0; s16 < GBKH / 16; s16++) {
                const uint32_t kb = sbase + s16 * 32;
                uint32_t af[4][4], bf[4][2];
#pragma unroll
                for (int mt = 0; mt < 4; mt++)
                    LDSM_X4(af[mt][0], af[mt][1], af[mt][2], af[mt][3],
                            kb + aOff[mt]);
#pragma unroll
                for (int p = 0; p < 2; p++)
                    LDSM_X4(bf[2*p][0], bf[2*p][1], bf[2*p+1][0], bf[2*p+1][1],
                            kb + bOff[p]);
#pragma unroll
                for (int mt = 0; mt < 4; mt++)
#pragma unroll
                    for (int nt = 0; nt < 4; nt++)
                        MMA_F16(acc[mt][nt][0], acc[mt][nt][1],
                                acc[mt][nt][2], acc[mt][nt][3],
                                af[mt][0], af[mt][1], af[mt][2], af[mt][3],
                                bf[nt][0], bf[nt][1]);
            }
        }

        // epilogue
        void* Cbv; int Nw, c0;
        if (SPLIT && bn0 >= N1) { Cbv = C2; Nw = N2; c0 = bn0 - N1; }
        else                    { Cbv = C;  Nw = SPLIT ? N1 : N; c0 = bn0; }

#pragma unroll
        for (int mt = 0; mt < 4; mt++) {
            const int r0 = bm0 + wm + mt * 16 + g;
#pragma unroll
            for (int nt = 0; nt < 4; nt++) {
                const int cc = c0 + wn + nt * 8 + tg * 2;
                if (cc < Nw) {
                    if (ROPEQ) {
                        const int d = cc % QKD;
                        if (d >= NOPE) {
                            const int ip = (d - NOPE) >> 1;
                            {
                                const float cv = g_cos[(size_t)r0 * 32 + ip];
                                const float sv = g_sin[(size_t)r0 * 32 + ip];
                                const float e = acc[mt][nt][0], o = acc[mt][nt][1];
                                acc[mt][nt][0] = e * cv - o * sv;
                                acc[mt][nt][1] = o * cv + e * sv;
                            }
                            {
                                const float cv = g_cos[(size_t)(r0 + 8) * 32 + ip];
                                const float sv = g_sin[(size_t)(r0 + 8) * 32 + ip];
                                const float e = acc[mt][nt][2], o = acc[mt][nt][3];
                                acc[mt][nt][2] = e * cv - o * sv;
                                acc[mt][nt][3] = o * cv + e * sv;
                            }
                        }
                    }
                    if (HALF_OUT) {
                        __half* Ch = (__half*)Cbv;
                        *reinterpret_cast<__half2*>(&Ch[(size_t)r0 * Nw + cc]) =
                            __floats2half2_rn(acc[mt][nt][0], acc[mt][nt][1]);
                        *reinterpret_cast<__half2*>(&Ch[(size_t)(r0 + 8) * Nw + cc]) =
                            __floats2half2_rn(acc[mt][nt][2], acc[mt][nt][3]);
                    } else {
                        float* Cf = (float*)Cbv;
                        *reinterpret_cast<float2*>(&Cf[(size_t)r0 * Nw + cc]) =
                            make_float2(acc[mt][nt][0], acc[mt][nt][1]);
                        *reinterpret_cast<float2*>(&Cf[(size_t)(r0 + 8) * Nw + cc]) =
                            make_float2(acc[mt][nt][2], acc[mt][nt][3]);
                    }
                }
            }
        }

        // drain pipeline and make smem safe for the next tile
        asm volatile("cp.async.wait_group 0;");
        __syncthreads();
    }
}

// ---------------------------------------------------------------------------
// RMSNorm — half in/out, 8-half (16B) vectorized, reduction in fp32.
// ---------------------------------------------------------------------------
__global__ void __launch_bounds__(256) rmsnorm_kernel(
    const __half* __restrict__ src, __half* __restrict__ dst,
    const float* __restrict__ w, int R, int sstride, int dstride)
{
    const int row = blockIdx.x;
    const h8* s8 = reinterpret_cast<const h8*>(src + (size_t)row * sstride);
    h8* d8 = reinterpret_cast<h8*>(dst + (size_t)row * dstride);
    const float4* w4 = reinterpret_cast<const float4*>(w);
    const int n8 = R >> 3;

    float sum = 0.f;
    for (int i = threadIdx.x; i < n8; i += 256) {
        const h8 v = s8[i];
#pragma unroll
        for (int j = 0; j < 4; j++) {
            const float2 p = __half22float2(v.h[j]);
            sum = fmaf(p.x, p.x, sum);
            sum = fmaf(p.y, p.y, sum);
        }
    }
    __shared__ float red[8];
#pragma unroll
    for (int o = 16; o; o >>= 1) sum += __shfl_down_sync(0xffffffffu, sum, o);
    if ((threadIdx.x & 31) == 0) red[threadIdx.x >> 5] = sum;
    __syncthreads();
    if (threadIdx.x < 8) {
        float v = red[threadIdx.x];
#pragma unroll
        for (int o = 4; o; o >>= 1) v += __shfl_down_sync(0xffu, v, o);
        if (threadIdx.x == 0) red[0] = v;
    }
    __syncthreads();
    const float mean = red[0] / (float)R;
    const float r = rsqrtf(mean + EPSF);

    for (int i = threadIdx.x; i < n8; i += 256) {
        const h8 v = s8[i];
        const float4 w0 = w4[2 * i];
        const float4 w1 = w4[2 * i + 1];
        const float2 a = __half22float2(v.h[0]);
        const float2 b = __half22float2(v.h[1]);
        const float2 c = __half22float2(v.h[2]);
        const float2 d = __half22float2(v.h[3]);
        h8 o;
        o.h[0] = __floats2half2_rn(a.x * r * w0.x, a.y * r * w0.y);
        o.h[1] = __floats2half2_rn(b.x * r * w0.z, b.y * r * w0.w);
        o.h[2] = __floats2half2_rn(c.x * r * w1.x, c.y * r * w1.y);
        o.h[3] = __floats2half2_rn(d.x * r * w1.z, d.y * r * w1.w);
        d8[i] = o;
    }
}

// ---------------------------------------------------------------------------
// RoPE tables + k_rope
// ---------------------------------------------------------------------------
__global__ void rope_tables_kernel()
{
    const int idx = blockIdx.x * blockDim.x + threadIdx.x;
    if (idx >= SEQ * (ROPE_D / 2)) return;
    const int t = idx / (ROPE_D / 2);
    const int i = idx % (ROPE_D / 2);
    const double freq = pow(500000.0, -(double)i / 32.0);
    const float ang = (float)t * (float)freq;
    g_cos[idx] = cosf(ang);
    g_sin[idx] = sinf(ang);
}

__global__ void rope_k_kernel()
{
    const int idx = blockIdx.x * blockDim.x + threadIdx.x;
    if (idx >= SEQ * (ROPE_D / 2)) return;
    const int i = idx & 31;
    const int t = idx >> 5;
    const float c = g_cos[t * 32 + i];
    const float s = g_sin[t * 32 + i];
    const __half2 src = *reinterpret_cast<const __half2*>(
        g_kvh + (size_t)t * (KVR + ROPE_D) + KVR + 2 * i);
    const float2 eo = __half22float2(src);
    *reinterpret_cast<__half2*>(g_kropeh + t * ROPE_D + 2 * i) =
        __floats2half2_rn(eo.x * c - eo.y * s, eo.y * c + eo.x * s);
}

// ---------------------------------------------------------------------------
// fp16 causal flash attention (unchanged from R13)
// ---------------------------------------------------------------------------
constexpr int QSH2  = 200;
constexpr int KVSH  = 264;
constexpr int KRSH  = 72;
constexpr int ATT_Q_BYTES  = 128 * QSH2 * 2;
constexpr int ATT_KV_BYTES = 64 * KVSH * 2;
constexpr int ATT_KR_BYTES = 64 * KRSH * 2;
constexpr int ATT_SMEM_BYTES =
    ATT_Q_BYTES + 2 * ATT_KV_BYTES + 2 * ATT_KR_BYTES;

__global__ void __launch_bounds__(256) attn_f16_kernel()
{
    extern __shared__ __half smh[];

    const int tid  = threadIdx.x;
    const int warp = tid >> 5;
    const int lane = tid & 31;
    const int g    = lane >> 2;
    const int tg   = lane & 3;
    const int bx   = blockIdx.x;
    const int qt   = (bx & 1) ? (15 - (bx >> 1)) : (bx >> 1);
    const int h    = blockIdx.y;
    const int qbase = qt * 128;
    const int r0   = warp * 16;

    const uint32_t s0   = (uint32_t)__cvta_generic_to_shared(smh);
    const uint32_t q_sm = s0;
    const uint32_t kv0  = s0 + ATT_Q_BYTES;
    const uint32_t kr0  = kv0 + 2 * ATT_KV_BYTES;

    auto load_q = [&]() {
#pragma unroll
        for (int i = 0; i < 12; i++) {
            const int c   = tid + i * 256;
            const int row = c / 24;
            const int seg = c % 24;
            const uint32_t d = q_sm + (row * QSH2 + seg * 8) * 2;
            const __half* gq = g_qh + (size_t)(qbase + row) * (NH * QKD)
                             + h * QKD + seg * 8;
            CP_ASYNC16(d, gq);
        }
    };
    auto load_kv = [&](int stage, int kbase) {
        const uint32_t kv = kv0 + stage * ATT_KV_BYTES;
        const uint32_t kr = kr0 + stage * ATT_KR_BYTES;
#pragma unroll
        for (int i = 0; i < 8; i++) {
            const int c   = tid + i * 256;
            const int row = c >> 5;
            const int seg = c & 31;
            const uint32_t d = kv + (row * KVSH + seg * 8) * 2;
            const __half* gk = g_kvuph + (size_t)(kbase + row) * (NH * KVUP_D)
                             + h * KVUP_D + seg * 8;
            CP_ASYNC16(d, gk);
        }
#pragma unroll
        for (int i = 0; i < 2; i++) {
            const int c   = tid + i * 256;
            const int row = c >> 3;
            const int seg = c & 7;
            const uint32_t d = kr + (row * KRSH + seg * 8) * 2;
            const __half* gr = g_kropeh + (size_t)(kbase + row) * ROPE_D
                             + seg * 8;
            CP_ASYNC16(d, gr);
        }
    };

    const int aRow = lane & 15;
    const int aK8  = (lane >> 4) * 8;
    const uint32_t qa_off = q_sm + ((r0 + aRow) * QSH2 + aK8) * 2;
    const int bRowL = (lane & 7) + ((lane & 16) ? 8 : 0);
    const int bK8   = lane & 8;
    const int vRow = lane & 15;
    const int vCol = (lane >> 4) * 8;

    float sacc[8][4];
    float oacc[16][4];
#pragma unroll
    for (int nv = 0; nv < 16; nv++)
#pragma unroll
        for (int v = 0; v < 4; v++) oacc[nv][v] = 0.f;
    float m0 = -INFINITY, m1 = -INFINITY, l0 = 0.f, l1 = 0.f;

    const int nkt = 2 * qt + 2;

    load_q();
    load_kv(0, 0);
    asm volatile("cp.async.commit_group;");

    for (int kt = 0; kt < nkt; kt++) {
        const int kbase = kt * 64;

        if (kt + 1 < nkt) {
            load_kv((kt + 1) & 1, (kt + 1) * 64);
            asm volatile("cp.async.commit_group;");
            asm volatile("cp.async.wait_group 1;");
        } else {
            asm volatile("cp.async.wait_group 0;");
        }
        __syncthreads();

        const uint32_t kv = kv0 + (kt & 1) * ATT_KV_BYTES;
        const uint32_t kr = kr0 + (kt & 1) * ATT_KR_BYTES;

#pragma unroll
        for (int nf = 0; nf < 8; nf++)
#pragma unroll
            for (int v = 0; v < 4; v++) sacc[nf][v] = 0.f;

#pragma unroll
        for (int s16 = 0; s16 < 12; s16++) {
            uint32_t a0, a1, a2, a3;
            LDSM_X4(a0, a1, a2, a3, qa_off + s16 * 32);
#pragma unroll
            for (int nfp = 0; nfp < 4; nfp++) {
                uint32_t b0, b1, b2, b3;
                if (s16 < 8) {
                    LDSM_X4(b0, b1, b2, b3,
                            kv + ((nfp * 16 + bRowL) * KVSH + bK8) * 2
                               + s16 * 32);
                } else {
                    LDSM_X4(b0, b1, b2, b3,
                            kr + ((nfp * 16 + bRowL) * KRSH + bK8) * 2
                               + (s16 - 8) * 32);
                }
                MMA_F16(sacc[2*nfp][0], sacc[2*nfp][1],
                        sacc[2*nfp][2], sacc[2*nfp][3],
                        a0, a1, a2, a3, b0, b1);
                MMA_F16(sacc[2*nfp+1][0], sacc[2*nfp+1][1],
                        sacc[2*nfp+1][2], sacc[2*nfp+1][3],
                        a0, a1, a2, a3, b2, b3);
            }
        }

        const int rg = qbase + r0 + g;
        if (kbase + 63 > rg) {
#pragma unroll
            for (int nf = 0; nf < 8; nf++) {
                const int c0 = kbase + nf * 8 + tg * 2;
                if (c0     > rg)     sacc[nf][0] = -INFINITY;
                if (c0 + 1 > rg)     sacc[nf][1] = -INFINITY;
                if (c0     > rg + 8) sacc[nf][2] = -INFINITY;
                if (c0 + 1 > rg + 8) sacc[nf][3] = -INFINITY;
            }
        }

        float t0 = -INFINITY, t1 = -INFINITY;
#pragma unroll
        for (int nf = 0; nf < 8; nf++) {
            t0 = fmaxf(t0, fmaxf(sacc[nf][0], sacc[nf][1]));
            t1 = fmaxf(t1, fmaxf(sacc[nf][2], sacc[nf][3]));
        }
        t0 = fmaxf(t0, __shfl_xor_sync(0xffffffffu, t0, 1));
        t0 = fmaxf(t0, __shfl_xor_sync(0xffffffffu, t0, 2));
        t1 = fmaxf(t1, __shfl_xor_sync(0xffffffffu, t1, 1));
        t1 = fmaxf(t1, __shfl_xor_sync(0xffffffffu, t1, 2));
        const float nm0 = fmaxf(m0, t0), nm1 = fmaxf(m1, t1);
        const float al0 = __expf(m0 - nm0), al1 = __expf(m1 - nm1);
        m0 = nm0; m1 = nm1;

        float rs0 = 0.f, rs1 = 0.f;
#pragma unroll
        for (int nf = 0; nf < 8; nf++) {
            sacc[nf][0] = __expf(sacc[nf][0] - nm0);
            sacc[nf][1] = __expf(sacc[nf][1] - nm0);
            sacc[nf][2] = __expf(sacc[nf][2] - nm1);
            sacc[nf][3] = __expf(sacc[nf][3] - nm1);
            rs0 += sacc[nf][0] + sacc[nf][1];
            rs1 += sacc[nf][2] + sacc[nf][3];
        }
        rs0 += __shfl_xor_sync(0xffffffffu, rs0, 1);
        rs0 += __shfl_xor_sync(0xffffffffu, rs0, 2);
        rs1 += __shfl_xor_sync(0xffffffffu, rs1, 1);
        rs1 += __shfl_xor_sync(0xffffffffu, rs1, 2);
        l0 = l0 * al0 + rs0;
        l1 = l1 * al1 + rs1;

#pragma unroll
        for (int nv = 0; nv < 16; nv++) {
            oacc[nv][0] *= al0; oacc[nv][1] *= al0;
            oacc[nv][2] *= al1; oacc[nv][3] *= al1;
        }

#pragma unroll
        for (int s = 0; s < 4; s++) {
            const uint32_t pa0 = packh2(sacc[2*s][0],   sacc[2*s][1]);
            const uint32_t pa1 = packh2(sacc[2*s][2],   sacc[2*s][3]);
            const uint32_t pa2 = packh2(sacc[2*s+1][0], sacc[2*s+1][1]);
            const uint32_t pa3 = packh2(sacc[2*s+1][2], sacc[2*s+1][3]);
#pragma unroll
            for (int nvp = 0; nvp < 8; nvp++) {
                uint32_t b0, b1, b2, b3;
                LDSM_X4_T(b0, b1, b2, b3,
                          kv + ((s * 16 + vRow) * KVSH
                               + NOPE + nvp * 16 + vCol) * 2);
                MMA_F16(oacc[2*nvp][0], oacc[2*nvp][1],
                        oacc[2*nvp][2], oacc[2*nvp][3],
                        pa0, pa1, pa2, pa3, b0, b1);
                MMA_F16(oacc[2*nvp+1][0], oacc[2*nvp+1][1],
                        oacc[2*nvp+1][2], oacc[2*nvp+1][3],
                        pa0, pa1, pa2, pa3, b2, b3);
            }
        }
        __syncthreads();
    }

    const float inv0 = 1.f / l0, inv1 = 1.f / l1;
    const int rga = qbase + r0 + g;
#pragma unroll
    for (int nv = 0; nv < 16; nv++) {
        const int col = h * VDIM + nv * 8 + tg * 2;
        *reinterpret_cast<__half2*>(&g_attnh[(size_t)rga * (NH * VDIM) + col]) =
            __floats2half2_rn(oacc[nv][0] * inv0, oacc[nv][1] * inv0);
        *reinterpret_cast<__half2*>(&g_attnh[(size_t)(rga + 8) * (NH * VDIM) + col]) =
            __floats2half2_rn(oacc[nv][2] * inv1, oacc[nv][3] * inv1);
    }
}

// ---------------------------------------------------------------------------
// Launch helpers
// ---------------------------------------------------------------------------
static inline int gemm_grid(int M, int N)
{
    const int ntiles = ((N + GBN - 1) / GBN) * (M / GBM);
    return ntiles < NSM_SLOTS ? ntiles : NSM_SLOTS;
}
static inline void launch_gemm_h(const __half* A, const __half* B, __half* C,
                                 int M, int N, int K)
{
    gemm_f16_kernel<false, true, false><<<gemm_grid(M, N), 256, GEMM_SMEM>>>(
        A, B, C, nullptr, M, N, N, 0, K);
}
static inline void launch_gemm_h_rope(const __half* A, const __half* B,
                                      __half* C, int M, int N, int K)
{
    gemm_f16_kernel<false, true, true><<<gemm_grid(M, N), 256, GEMM_SMEM>>>(
        A, B, C, nullptr, M, N, N, 0, K);
}
static inline void launch_gemm_f(const __half* A, const __half* B, float* C,
                                 int M, int N, int K)
{
    gemm_f16_kernel<false, false, false><<<gemm_grid(M, N), 256, GEMM_SMEM>>>(
        A, B, C, nullptr, M, N, N, 0, K);
}
static inline void launch_gemm_split_h(const __half* A, const __half* B,
                                       __half* C1, __half* C2,
                                       int M, int N1, int N2, int K)
{
    const int N = N1 + N2;
    gemm_f16_kernel<true, true, false><<<gemm_grid(M, N), 256, GEMM_SMEM>>>(
        A, B, C1, C2, M, N, N1, N2, K);
}
static inline void launch_f2h(const float* src, __half* dst, int n,
                              float scale = 1.f)
{
    const int n8 = n / 8;
    int grid = (n8 + 1023) / 1024;
    if (grid > 592) grid = 592;
    f2h_kernel<<<grid, 256>>>((const float4*)src, (h8*)dst, n8, scale);
}

extern "C" void kernel_launch(void* const* d_in, const int* in_sizes, int n_in,
                              void* d_out, int out_size)
{
    const float* x         = (const float*)d_in[0];
    const float* w_q_down  = (const float*)d_in[1];
    const float* q_norm_w  = (const float*)d_in[2];
    const float* w_q_up    = (const float*)d_in[3];
    const float* w_kv_down = (const float*)d_in[4];
    const float* kv_norm_w = (const float*)d_in[5];
    const float* w_kv_up   = (const float*)d_in[6];
    const float* w_o       = (const float*)d_in[7];
    float* out = (float*)d_out;

    __half *cqh, *kvh, *ckvh, *qh, *kvuph, *attnh;
    __half *xh, *wqkvdh, *wquh, *wkvuh, *woh;
    cudaGetSymbolAddress((void**)&cqh,    g_cqh);
    cudaGetSymbolAddress((void**)&kvh,    g_kvh);
    cudaGetSymbolAddress((void**)&ckvh,   g_ckvh);
    cudaGetSymbolAddress((void**)&qh,     g_qh);
    cudaGetSymbolAddress((void**)&kvuph,  g_kvuph);
    cudaGetSymbolAddress((void**)&attnh,  g_attnh);
    cudaGetSymbolAddress((void**)&xh,     g_xh);
    cudaGetSymbolAddress((void**)&wqkvdh, g_wqkvdh);
    cudaGetSymbolAddress((void**)&wquh,   g_wquh);
    cudaGetSymbolAddress((void**)&wkvuh,  g_wkvuh);
    cudaGetSymbolAddress((void**)&woh,    g_woh);

    cudaFuncSetAttribute(attn_f16_kernel,
                         cudaFuncAttributeMaxDynamicSharedMemorySize,
                         ATT_SMEM_BYTES);
    cudaFuncSetAttribute((void*)gemm_f16_kernel<false, true, false>,
                         cudaFuncAttributeMaxDynamicSharedMemorySize, GEMM_SMEM);
    cudaFuncSetAttribute((void*)gemm_f16_kernel<false, true, true>,
                         cudaFuncAttributeMaxDynamicSharedMemorySize, GEMM_SMEM);
    cudaFuncSetAttribute((void*)gemm_f16_kernel<false, false, false>,
                         cudaFuncAttributeMaxDynamicSharedMemorySize, GEMM_SMEM);
    cudaFuncSetAttribute((void*)gemm_f16_kernel<true, true, false>,
                         cudaFuncAttributeMaxDynamicSharedMemorySize, GEMM_SMEM);

    const float qscale = 0.07216878364870322f;  // 1/sqrt(192)

    // 0. rope tables (needed by q-GEMM epilogue) + half conversions
    rope_tables_kernel<<<(SEQ * 32 + 255) / 256, 256>>>();
    launch_f2h(x,         xh,                SEQ * DIM);
    launch_f2h(w_q_down,  wqkvdh,            QR * DIM);
    launch_f2h(w_kv_down, wqkvdh + QR * DIM, (KVR + ROPE_D) * DIM);
    launch_f2h(w_q_up,    wquh,              NH * QKD * QR, qscale);
    launch_f2h(w_kv_up,   wkvuh,             NH * KVUP_D * KVR);
    launch_f2h(w_o,       woh,               DIM * NH * VDIM);

    // 1. [c_q_pre | kv] = x @ [w_q_down; w_kv_down].T  (half outputs)
    launch_gemm_split_h(xh, wqkvdh, cqh, kvh, SEQ, QR, KVR + ROPE_D, DIM);
    // 2. c_q = rmsnorm(c_q_pre) (in place, vectorized)
    rmsnorm_kernel<<<SEQ, 256>>>(cqh, cqh, q_norm_w, QR, QR, QR);
    // 3. q = c_q @ (w_q_up * scale).T with fused RoPE -> half
    launch_gemm_h_rope(cqh, wquh, qh, SEQ, NH * QKD, QR);
    // 4. c_kv = rmsnorm(kv[:, :512]) -> half
    rmsnorm_kernel<<<SEQ, 256>>>(kvh, ckvh, kv_norm_w, KVR, KVR + ROPE_D, KVR);
    // 5. k_rope
    rope_k_kernel<<<(SEQ * 32 + 255) / 256, 256>>>();
    // 6. kv_up = c_kv @ w_kv_up.T -> half
    launch_gemm_h(ckvh, wkvuh, kvuph, SEQ, NH * KVUP_D, KVR);
    // 7. pipelined fp16 causal attention -> g_attnh
    attn_f16_kernel<<<dim3(SEQ / 128, NH), 256, ATT_SMEM_BYTES>>>();
    // 8. out = attn @ w_o.T (fp32 out)
    launch_gemm_f(attnh, woh, out, SEQ, DIM, NH * VDIM);
}

// round 15
// speedup vs baseline: 1.0446x; 1.0446x over previous
#include <cuda_runtime.h>
#include <cuda_fp16.h>
#include <math.h>
#include <stdint.h>

// ---------------------------------------------------------------------------
// Problem constants
// ---------------------------------------------------------------------------
constexpr int SEQ    = 2048;
constexpr int DIM    = 2048;
constexpr int NH     = 16;
constexpr int QR     = 1536;
constexpr int KVR    = 512;
constexpr int ROPE_D = 64;
constexpr int NOPE   = 128;
constexpr int VDIM   = 128;
constexpr int QKD    = NOPE + ROPE_D;          // 192
constexpr int KVUP_D = NOPE + VDIM;            // 256
constexpr float EPSF = 1e-6f;

// ---------------------------------------------------------------------------
// Scratch (device globals: allocation-free) — all-half intermediates
// ---------------------------------------------------------------------------
__device__ __align__(256) __half g_cqh  [SEQ * QR];
__device__ __align__(256) __half g_kvh  [SEQ * (KVR + ROPE_D)];
__device__ __align__(256) __half g_ckvh [SEQ * KVR];
__device__ __align__(256) __half g_qh   [SEQ * NH * QKD];      // scaled + roped
__device__ __align__(256) __half g_kropeh[SEQ * ROPE_D];
__device__ __align__(256) __half g_kvuph[SEQ * NH * KVUP_D];   // k_nope | v
__device__ __align__(256) __half g_attnh[SEQ * NH * VDIM];
__device__ __align__(256) float  g_cos  [SEQ * (ROPE_D / 2)];
__device__ __align__(256) float  g_sin  [SEQ * (ROPE_D / 2)];
// half operand copies
__device__ __align__(256) __half g_xh   [SEQ * DIM];
__device__ __align__(256) __half g_wqkvdh[(QR + KVR + ROPE_D) * DIM];
__device__ __align__(256) __half g_wquh [NH * QKD * QR];       // pre-scaled
__device__ __align__(256) __half g_wkvuh[NH * KVUP_D * KVR];
__device__ __align__(256) __half g_woh  [DIM * NH * VDIM];

// ---------------------------------------------------------------------------
// helpers
// ---------------------------------------------------------------------------
__device__ __forceinline__ uint32_t packh2(float a, float b) {
    __half2 h = __floats2half2_rn(a, b);
    return *reinterpret_cast<uint32_t*>(&h);
}

#define MMA_F16(D0,D1,D2,D3,A0,A1,A2,A3,B0,B1)                               \
    asm volatile(                                                            \
        "mma.sync.aligned.m16n8k16.row.col.f32.f16.f16.f32 "                 \
        "{%0,%1,%2,%3},{%4,%5,%6,%7},{%8,%9},{%0,%1,%2,%3};"                 \
        : "+f"(D0), "+f"(D1), "+f"(D2), "+f"(D3)                             \
        : "r"(A0), "r"(A1), "r"(A2), "r"(A3), "r"(B0), "r"(B1))

#define LDSM_X4(R0,R1,R2,R3,ADDR)                                            \
    asm volatile(                                                            \
        "ldmatrix.sync.aligned.m8n8.x4.shared.b16 {%0,%1,%2,%3}, [%4];"      \
        : "=r"(R0), "=r"(R1), "=r"(R2), "=r"(R3) : "r"(ADDR))

#define LDSM_X4_T(R0,R1,R2,R3,ADDR)                                          \
    asm volatile(                                                            \
        "ldmatrix.sync.aligned.m8n8.x4.trans.shared.b16 {%0,%1,%2,%3}, [%4];"\
        : "=r"(R0), "=r"(R1), "=r"(R2), "=r"(R3) : "r"(ADDR))

#define CP_ASYNC16(DST,SRC)                                                  \
    asm volatile("cp.async.cg.shared.global [%0], [%1], 16;"                 \
                 :: "r"(DST), "l"(SRC))

// 16-byte half vector (8 halves)
struct __align__(16) h8 { __half2 h[4]; };

// ---------------------------------------------------------------------------
// float -> half conversion (reads 2 float4 = 8 floats, writes one h8)
// ---------------------------------------------------------------------------
__global__ void __launch_bounds__(256) f2h_kernel(
    const float4* __restrict__ src, h8* __restrict__ dst, int n8, float scale)
{
    for (int i = blockIdx.x * 256 + threadIdx.x; i < n8; i += gridDim.x * 256) {
        const float4 v0 = src[2 * i];
        const float4 v1 = src[2 * i + 1];
        h8 o;
        o.h[0] = __floats2half2_rn(v0.x * scale, v0.y * scale);
        o.h[1] = __floats2half2_rn(v0.z * scale, v0.w * scale);
        o.h[2] = __floats2half2_rn(v1.x * scale, v1.y * scale);
        o.h[3] = __floats2half2_rn(v1.z * scale, v1.w * scale);
        dst[i] = o;
    }
}

// ---------------------------------------------------------------------------
// fp16 NT GEMM: C[M,N] = A[M,K](f16) * B[N,K](f16)^T  (R13 fixed-grid version)
// 128x128 CTA, 8 warps x (64x32), m16n8k16, ldmatrix, 3-stage cp.async.
// HALF_OUT: write __half. SPLIT: cols [0,N1)->C, [N1,N)->C2.
// ROPEQ: fused RoPE on columns with (col % 192) >= 128 (rows = tokens).
// ---------------------------------------------------------------------------
constexpr int GBM = 128, GBN = 128, GBKH = 64, HSTR = 72;
constexpr int GTILE_H = (GBM + GBN) * HSTR;
constexpr int GSTAGES = 3;
constexpr int GEMM_SMEM = GSTAGES * GTILE_H * 2;
constexpr int A_OFF_B  = GBM * HSTR * 2;

template<bool SPLIT, bool HALF_OUT, bool ROPEQ>
__global__ void __launch_bounds__(256, 2) gemm_f16_kernel(
    const __half* __restrict__ A, const __half* __restrict__ B,
    void* __restrict__ C, void* __restrict__ C2,
    int M, int N, int N1, int N2, int K)
{
    extern __shared__ __half smh[];

    const int tid  = threadIdx.x;
    const int warp = tid >> 5;
    const int lane = tid & 31;
    const int g    = lane >> 2;
    const int tg   = lane & 3;
    const int wm   = (warp & 1) * 64;
    const int wn   = (warp >> 1) * 32;
    const int bm0  = blockIdx.y * GBM;
    const int bn0  = blockIdx.x * GBN;

    const uint32_t s0 = (uint32_t)__cvta_generic_to_shared(smh);

    auto load_tiles = [&](int slot, int k0) {
        const uint32_t sA = s0 + slot * (GTILE_H * 2);
        const uint32_t sB = sA + A_OFF_B;
#pragma unroll
        for (int i = 0; i < 4; i++) {
            const int c   = tid + i * 256;
            const int row = c >> 3;
            const int seg = c & 7;
            const uint32_t da = sA + (row * HSTR + seg * 8) * 2;
            const __half* ga = A + (size_t)(bm0 + row) * K + k0 + seg * 8;
            CP_ASYNC16(da, ga);
        }
#pragma unroll
        for (int i = 0; i < 4; i++) {
            const int c   = tid + i * 256;
            const int row = c >> 3;
            const int seg = c & 7;
            const int rb  = bn0 + row;
            const int ok  = (rb < N) ? 16 : 0;
            const __half* gb = B + (size_t)(ok ? rb : 0) * K + k0 + seg * 8;
            const uint32_t db = sB + (row * HSTR + seg * 8) * 2;
            asm volatile("cp.async.cg.shared.global [%0], [%1], 16, %2;"
                         :: "r"(db), "l"(gb), "r"(ok));
        }
    };

    float acc[4][4][4];
#pragma unroll
    for (int mt = 0; mt < 4; mt++)
#pragma unroll
        for (int nt = 0; nt < 4; nt++)
#pragma unroll
            for (int v = 0; v < 4; v++) acc[mt][nt][v] = 0.f;

    const int nk = K / GBKH;

#pragma unroll
    for (int s = 0; s < GSTAGES - 1; s++) {
        if (s < nk) load_tiles(s, s * GBKH);
        asm volatile("cp.async.commit_group;");
    }

    const int aRow = lane & 15;
    const int aK8  = (lane >> 4) * 8;
    uint32_t aOff[4];
#pragma unroll
    for (int mt = 0; mt < 4; mt++)
        aOff[mt] = ((wm + mt * 16 + aRow) * HSTR + aK8) * 2;
    const int bRowL = (lane & 7) + ((lane & 16) ? 8 : 0);
    const int bK8   = lane & 8;
    uint32_t bOff[2];
#pragma unroll
    for (int p = 0; p < 2; p++)
        bOff[p] = ((wn + p * 16 + bRowL) * HSTR + bK8) * 2 + A_OFF_B;

    for (int kt = 0; kt < nk; kt++) {
        asm volatile("cp.async.wait_group %0;" :: "n"(GSTAGES - 2));
        __syncthreads();

        if (kt + GSTAGES - 1 < nk)
            load_tiles((kt + GSTAGES - 1) % GSTAGES, (kt + GSTAGES - 1) * GBKH);
        asm volatile("cp.async.commit_group;");

        const uint32_t sbase = s0 + (kt % GSTAGES) * (GTILE_H * 2);

#pragma unroll
        for (int s16 = 0; s16 < GBKH / 16; s16++) {
            const uint32_t kb = sbase + s16 * 32;
            uint32_t af[4][4], bf[4][2];
#pragma unroll
            for (int mt = 0; mt < 4; mt++)
                LDSM_X4(af[mt][0], af[mt][1], af[mt][2], af[mt][3],
                        kb + aOff[mt]);
#pragma unroll
            for (int p = 0; p < 2; p++)
                LDSM_X4(bf[2*p][0], bf[2*p][1], bf[2*p+1][0], bf[2*p+1][1],
                        kb + bOff[p]);
#pragma unroll
            for (int mt = 0; mt < 4; mt++)
#pragma unroll
                for (int nt = 0; nt < 4; nt++)
                    MMA_F16(acc[mt][nt][0], acc[mt][nt][1],
                            acc[mt][nt][2], acc[mt][nt][3],
                            af[mt][0], af[mt][1], af[mt][2], af[mt][3],
                            bf[nt][0], bf[nt][1]);
        }
    }

    void* Cbv; int Nw, c0;
    if (SPLIT && bn0 >= N1) { Cbv = C2; Nw = N2; c0 = bn0 - N1; }
    else                    { Cbv = C;  Nw = SPLIT ? N1 : N; c0 = bn0; }

#pragma unroll
    for (int mt = 0; mt < 4; mt++) {
        const int r0 = bm0 + wm + mt * 16 + g;
#pragma unroll
        for (int nt = 0; nt < 4; nt++) {
            const int cc = c0 + wn + nt * 8 + tg * 2;
            if (cc < Nw) {
                if (ROPEQ) {
                    const int d = cc % QKD;
                    if (d >= NOPE) {
                        const int ip = (d - NOPE) >> 1;
                        {
                            const float cv = g_cos[(size_t)r0 * 32 + ip];
                            const float sv = g_sin[(size_t)r0 * 32 + ip];
                            const float e = acc[mt][nt][0], o = acc[mt][nt][1];
                            acc[mt][nt][0] = e * cv - o * sv;
                            acc[mt][nt][1] = o * cv + e * sv;
                        }
                        {
                            const float cv = g_cos[(size_t)(r0 + 8) * 32 + ip];
                            const float sv = g_sin[(size_t)(r0 + 8) * 32 + ip];
                            const float e = acc[mt][nt][2], o = acc[mt][nt][3];
                            acc[mt][nt][2] = e * cv - o * sv;
                            acc[mt][nt][3] = o * cv + e * sv;
                        }
                    }
                }
                if (HALF_OUT) {
                    __half* Ch = (__half*)Cbv;
                    *reinterpret_cast<__half2*>(&Ch[(size_t)r0 * Nw + cc]) =
                        __floats2half2_rn(acc[mt][nt][0], acc[mt][nt][1]);
                    *reinterpret_cast<__half2*>(&Ch[(size_t)(r0 + 8) * Nw + cc]) =
                        __floats2half2_rn(acc[mt][nt][2], acc[mt][nt][3]);
                } else {
                    float* Cf = (float*)Cbv;
                    *reinterpret_cast<float2*>(&Cf[(size_t)r0 * Nw + cc]) =
                        make_float2(acc[mt][nt][0], acc[mt][nt][1]);
                    *reinterpret_cast<float2*>(&Cf[(size_t)(r0 + 8) * Nw + cc]) =
                        make_float2(acc[mt][nt][2], acc[mt][nt][3]);
                }
            }
        }
    }
}

// ---------------------------------------------------------------------------
// RMSNorm — half in/out, 8-half (16B) vectorized, reduction in fp32.
// ---------------------------------------------------------------------------
__global__ void __launch_bounds__(256) rmsnorm_kernel(
    const __half* __restrict__ src, __half* __restrict__ dst,
    const float* __restrict__ w, int R, int sstride, int dstride)
{
    const int row = blockIdx.x;
    const h8* s8 = reinterpret_cast<const h8*>(src + (size_t)row * sstride);
    h8* d8 = reinterpret_cast<h8*>(dst + (size_t)row * dstride);
    const float4* w4 = reinterpret_cast<const float4*>(w);
    const int n8 = R >> 3;

    float sum = 0.f;
    for (int i = threadIdx.x; i < n8; i += 256) {
        const h8 v = s8[i];
#pragma unroll
        for (int j = 0; j < 4; j++) {
            const float2 p = __half22float2(v.h[j]);
            sum = fmaf(p.x, p.x, sum);
            sum = fmaf(p.y, p.y, sum);
        }
    }
    __shared__ float red[8];
#pragma unroll
    for (int o = 16; o; o >>= 1) sum += __shfl_down_sync(0xffffffffu, sum, o);
    if ((threadIdx.x & 31) == 0) red[threadIdx.x >> 5] = sum;
    __syncthreads();
    if (threadIdx.x < 8) {
        float v = red[threadIdx.x];
#pragma unroll
        for (int o = 4; o; o >>= 1) v += __shfl_down_sync(0xffu, v, o);
        if (threadIdx.x == 0) red[0] = v;
    }
    __syncthreads();
    const float mean = red[0] / (float)R;
    const float r = rsqrtf(mean + EPSF);

    for (int i = threadIdx.x; i < n8; i += 256) {
        const h8 v = s8[i];
        const float4 w0 = w4[2 * i];
        const float4 w1 = w4[2 * i + 1];
        const float2 a = __half22float2(v.h[0]);
        const float2 b = __half22float2(v.h[1]);
        const float2 c = __half22float2(v.h[2]);
        const float2 d = __half22float2(v.h[3]);
        h8 o;
        o.h[0] = __floats2half2_rn(a.x * r * w0.x, a.y * r * w0.y);
        o.h[1] = __floats2half2_rn(b.x * r * w0.z, b.y * r * w0.w);
        o.h[2] = __floats2half2_rn(c.x * r * w1.x, c.y * r * w1.y);
        o.h[3] = __floats2half2_rn(d.x * r * w1.z, d.y * r * w1.w);
        d8[i] = o;
    }
}

// ---------------------------------------------------------------------------
// RoPE tables + k_rope
// ---------------------------------------------------------------------------
__global__ void rope_tables_kernel()
{
    const int idx = blockIdx.x * blockDim.x + threadIdx.x;
    if (idx >= SEQ * (ROPE_D / 2)) return;
    const int t = idx / (ROPE_D / 2);
    const int i = idx % (ROPE_D / 2);
    const double freq = pow(500000.0, -(double)i / 32.0);
    const float ang = (float)t * (float)freq;
    g_cos[idx] = cosf(ang);
    g_sin[idx] = sinf(ang);
}

__global__ void rope_k_kernel()
{
    const int idx = blockIdx.x * blockDim.x + threadIdx.x;
    if (idx >= SEQ * (ROPE_D / 2)) return;
    const int i = idx & 31;
    const int t = idx >> 5;
    const float c = g_cos[t * 32 + i];
    const float s = g_sin[t * 32 + i];
    const __half2 src = *reinterpret_cast<const __half2*>(
        g_kvh + (size_t)t * (KVR + ROPE_D) + KVR + 2 * i);
    const float2 eo = __half22float2(src);
    *reinterpret_cast<__half2*>(g_kropeh + t * ROPE_D + 2 * i) =
        __floats2half2_rn(eo.x * c - eo.y * s, eo.y * c + eo.x * s);
}

// ---------------------------------------------------------------------------
// fp16 causal flash attention (unchanged from R13)
// ---------------------------------------------------------------------------
constexpr int QSH2  = 200;
constexpr int KVSH  = 264;
constexpr int KRSH  = 72;
constexpr int ATT_Q_BYTES  = 128 * QSH2 * 2;
constexpr int ATT_KV_BYTES = 64 * KVSH * 2;
constexpr int ATT_KR_BYTES = 64 * KRSH * 2;
constexpr int ATT_SMEM_BYTES =
    ATT_Q_BYTES + 2 * ATT_KV_BYTES + 2 * ATT_KR_BYTES;

__global__ void __launch_bounds__(256) attn_f16_kernel()
{
    extern __shared__ __half smh[];

    const int tid  = threadIdx.x;
    const int warp = tid >> 5;
    const int lane = tid & 31;
    const int g    = lane >> 2;
    const int tg   = lane & 3;
    const int bx   = blockIdx.x;
    const int qt   = (bx & 1) ? (15 - (bx >> 1)) : (bx >> 1);
    const int h    = blockIdx.y;
    const int qbase = qt * 128;
    const int r0   = warp * 16;

    const uint32_t s0   = (uint32_t)__cvta_generic_to_shared(smh);
    const uint32_t q_sm = s0;
    const uint32_t kv0  = s0 + ATT_Q_BYTES;
    const uint32_t kr0  = kv0 + 2 * ATT_KV_BYTES;

    auto load_q = [&]() {
#pragma unroll
        for (int i = 0; i < 12; i++) {
            const int c   = tid + i * 256;
            const int row = c / 24;
            const int seg = c % 24;
            const uint32_t d = q_sm + (row * QSH2 + seg * 8) * 2;
            const __half* gq = g_qh + (size_t)(qbase + row) * (NH * QKD)
                             + h * QKD + seg * 8;
            CP_ASYNC16(d, gq);
        }
    };
    auto load_kv = [&](int stage, int kbase) {
        const uint32_t kv = kv0 + stage * ATT_KV_BYTES;
        const uint32_t kr = kr0 + stage * ATT_KR_BYTES;
#pragma unroll
        for (int i = 0; i < 8; i++) {
            const int c   = tid + i * 256;
            const int row = c >> 5;
            const int seg = c & 31;
            const uint32_t d = kv + (row * KVSH + seg * 8) * 2;
            const __half* gk = g_kvuph + (size_t)(kbase + row) * (NH * KVUP_D)
                             + h * KVUP_D + seg * 8;
            CP_ASYNC16(d, gk);
        }
#pragma unroll
        for (int i = 0; i < 2; i++) {
            const int c   = tid + i * 256;
            const int row = c >> 3;
            const int seg = c & 7;
            const uint32_t d = kr + (row * KRSH + seg * 8) * 2;
            const __half* gr = g_kropeh + (size_t)(kbase + row) * ROPE_D
                             + seg * 8;
            CP_ASYNC16(d, gr);
        }
    };

    const int aRow = lane & 15;
    const int aK8  = (lane >> 4) * 8;
    const uint32_t qa_off = q_sm + ((r0 + aRow) * QSH2 + aK8) * 2;
    const int bRowL = (lane & 7) + ((lane & 16) ? 8 : 0);
    const int bK8   = lane & 8;
    const int vRow = lane & 15;
    const int vCol = (lane >> 4) * 8;

    float sacc[8][4];
    float oacc[16][4];
#pragma unroll
    for (int nv = 0; nv < 16; nv++)
#pragma unroll
        for (int v = 0; v < 4; v++) oacc[nv][v] = 0.f;
    float m0 = -INFINITY, m1 = -INFINITY, l0 = 0.f, l1 = 0.f;

    const int nkt = 2 * qt + 2;

    load_q();
    load_kv(0, 0);
    asm volatile("cp.async.commit_group;");

    for (int kt = 0; kt < nkt; kt++) {
        const int kbase = kt * 64;

        if (kt + 1 < nkt) {
            load_kv((kt + 1) & 1, (kt + 1) * 64);
            asm volatile("cp.async.commit_group;");
            asm volatile("cp.async.wait_group 1;");
        } else {
            asm volatile("cp.async.wait_group 0;");
        }
        __syncthreads();

        const uint32_t kv = kv0 + (kt & 1) * ATT_KV_BYTES;
        const uint32_t kr = kr0 + (kt & 1) * ATT_KR_BYTES;

#pragma unroll
        for (int nf = 0; nf < 8; nf++)
#pragma unroll
            for (int v = 0; v < 4; v++) sacc[nf][v] = 0.f;

#pragma unroll
        for (int s16 = 0; s16 < 12; s16++) {
            uint32_t a0, a1, a2, a3;
            LDSM_X4(a0, a1, a2, a3, qa_off + s16 * 32);
#pragma unroll
            for (int nfp = 0; nfp < 4; nfp++) {
                uint32_t b0, b1, b2, b3;
                if (s16 < 8) {
                    LDSM_X4(b0, b1, b2, b3,
                            kv + ((nfp * 16 + bRowL) * KVSH + bK8) * 2
                               + s16 * 32);
                } else {
                    LDSM_X4(b0, b1, b2, b3,
                            kr + ((nfp * 16 + bRowL) * KRSH + bK8) * 2
                               + (s16 - 8) * 32);
                }
                MMA_F16(sacc[2*nfp][0], sacc[2*nfp][1],
                        sacc[2*nfp][2], sacc[2*nfp][3],
                        a0, a1, a2, a3, b0, b1);
                MMA_F16(sacc[2*nfp+1][0], sacc[2*nfp+1][1],
                        sacc[2*nfp+1][2], sacc[2*nfp+1][3],
                        a0, a1, a2, a3, b2, b3);
            }
        }

        const int rg = qbase + r0 + g;
        if (kbase + 63 > rg) {
#pragma unroll
            for (int nf = 0; nf < 8; nf++) {
                const int c0 = kbase + nf * 8 + tg * 2;
                if (c0     > rg)     sacc[nf][0] = -INFINITY;
                if (c0 + 1 > rg)     sacc[nf][1] = -INFINITY;
                if (c0     > rg + 8) sacc[nf][2] = -INFINITY;
                if (c0 + 1 > rg + 8) sacc[nf][3] = -INFINITY;
            }
        }

        float t0 = -INFINITY, t1 = -INFINITY;
#pragma unroll
        for (int nf = 0; nf < 8; nf++) {
            t0 = fmaxf(t0, fmaxf(sacc[nf][0], sacc[nf][1]));
            t1 = fmaxf(t1, fmaxf(sacc[nf][2], sacc[nf][3]));
        }
        t0 = fmaxf(t0, __shfl_xor_sync(0xffffffffu, t0, 1));
        t0 = fmaxf(t0, __shfl_xor_sync(0xffffffffu, t0, 2));
        t1 = fmaxf(t1, __shfl_xor_sync(0xffffffffu, t1, 1));
        t1 = fmaxf(t1, __shfl_xor_sync(0xffffffffu, t1, 2));
        const float nm0 = fmaxf(m0, t0), nm1 = fmaxf(m1, t1);
        const float al0 = __expf(m0 - nm0), al1 = __expf(m1 - nm1);
        m0 = nm0; m1 = nm1;

        float rs0 = 0.f, rs1 = 0.f;
#pragma unroll
        for (int nf = 0; nf < 8; nf++) {
            sacc[nf][0] = __expf(sacc[nf][0] - nm0);
            sacc[nf][1] = __expf(sacc[nf][1] - nm0);
            sacc[nf][2] = __expf(sacc[nf][2] - nm1);
            sacc[nf][3] = __expf(sacc[nf][3] - nm1);
            rs0 += sacc[nf][0] + sacc[nf][1];
            rs1 += sacc[nf][2] + sacc[nf][3];
        }
        rs0 += __shfl_xor_sync(0xffffffffu, rs0, 1);
        rs0 += __shfl_xor_sync(0xffffffffu, rs0, 2);
        rs1 += __shfl_xor_sync(0xffffffffu, rs1, 1);
        rs1 += __shfl_xor_sync(0xffffffffu, rs1, 2);
        l0 = l0 * al0 + rs0;
        l1 = l1 * al1 + rs1;

#pragma unroll
        for (int nv = 0; nv < 16; nv++) {
            oacc[nv][0] *= al0; oacc[nv][1] *= al0;
            oacc[nv][2] *= al1; oacc[nv][3] *= al1;
        }

#pragma unroll
        for (int s = 0; s < 4; s++) {
            const uint32_t pa0 = packh2(sacc[2*s][0],   sacc[2*s][1]);
            const uint32_t pa1 = packh2(sacc[2*s][2],   sacc[2*s][3]);
            const uint32_t pa2 = packh2(sacc[2*s+1][0], sacc[2*s+1][1]);
            const uint32_t pa3 = packh2(sacc[2*s+1][2], sacc[2*s+1][3]);
#pragma unroll
            for (int nvp = 0; nvp < 8; nvp++) {
                uint32_t b0, b1, b2, b3;
                LDSM_X4_T(b0, b1, b2, b3,
                          kv + ((s * 16 + vRow) * KVSH
                               + NOPE + nvp * 16 + vCol) * 2);
                MMA_F16(oacc[2*nvp][0], oacc[2*nvp][1],
                        oacc[2*nvp][2], oacc[2*nvp][3],
                        pa0, pa1, pa2, pa3, b0, b1);
                MMA_F16(oacc[2*nvp+1][0], oacc[2*nvp+1][1],
                        oacc[2*nvp+1][2], oacc[2*nvp+1][3],
                        pa0, pa1, pa2, pa3, b2, b3);
            }
        }
        __syncthreads();
    }

    const float inv0 = 1.f / l0, inv1 = 1.f / l1;
    const int rga = qbase + r0 + g;
#pragma unroll
    for (int nv = 0; nv < 16; nv++) {
        const int col = h * VDIM + nv * 8 + tg * 2;
        *reinterpret_cast<__half2*>(&g_attnh[(size_t)rga * (NH * VDIM) + col]) =
            __floats2half2_rn(oacc[nv][0] * inv0, oacc[nv][1] * inv0);
        *reinterpret_cast<__half2*>(&g_attnh[(size_t)(rga + 8) * (NH * VDIM) + col]) =
            __floats2half2_rn(oacc[nv][2] * inv1, oacc[nv][3] * inv1);
    }
}

// ---------------------------------------------------------------------------
// Launch helpers (stream-aware)
// ---------------------------------------------------------------------------
static inline void launch_gemm_h(const __half* A, const __half* B, __half* C,
                                 int M, int N, int K, cudaStream_t st)
{
    dim3 grid((N + GBN - 1) / GBN, M / GBM);
    gemm_f16_kernel<false, true, false><<<grid, 256, GEMM_SMEM, st>>>(
        A, B, C, nullptr, M, N, N, 0, K);
}
static inline void launch_gemm_h_rope(const __half* A, const __half* B,
                                      __half* C, int M, int N, int K,
                                      cudaStream_t st)
{
    dim3 grid((N + GBN - 1) / GBN, M / GBM);
    gemm_f16_kernel<false, true, true><<<grid, 256, GEMM_SMEM, st>>>(
        A, B, C, nullptr, M, N, N, 0, K);
}
static inline void launch_gemm_f(const __half* A, const __half* B, float* C,
                                 int M, int N, int K, cudaStream_t st)
{
    dim3 grid((N + GBN - 1) / GBN, M / GBM);
    gemm_f16_kernel<false, false, false><<<grid, 256, GEMM_SMEM, st>>>(
        A, B, C, nullptr, M, N, N, 0, K);
}
static inline void launch_gemm_split_h(const __half* A, const __half* B,
                                       __half* C1, __half* C2,
                                       int M, int N1, int N2, int K,
                                       cudaStream_t st)
{
    const int N = N1 + N2;
    dim3 grid((N + GBN - 1) / GBN, M / GBM);
    gemm_f16_kernel<true, true, false><<<grid, 256, GEMM_SMEM, st>>>(
        A, B, C1, C2, M, N, N1, N2, K);
}
static inline void launch_f2h(const float* src, __half* dst, int n,
                              float scale, cudaStream_t st)
{
    const int n8 = n / 8;
    int grid = (n8 + 1023) / 1024;
    if (grid > 592) grid = 592;
    f2h_kernel<<<grid, 256, 0, st>>>((const float4*)src, (h8*)dst, n8, scale);
}

extern "C" void kernel_launch(void* const* d_in, const int* in_sizes, int n_in,
                              void* d_out, int out_size)
{
    const float* x         = (const float*)d_in[0];
    const float* w_q_down  = (const float*)d_in[1];
    const float* q_norm_w  = (const float*)d_in[2];
    const float* w_q_up    = (const float*)d_in[3];
    const float* w_kv_down = (const float*)d_in[4];
    const float* kv_norm_w = (const float*)d_in[5];
    const float* w_kv_up   = (const float*)d_in[6];
    const float* w_o       = (const float*)d_in[7];
    float* out = (float*)d_out;

    __half *cqh, *kvh, *ckvh, *qh, *kvuph, *attnh;
    __half *xh, *wqkvdh, *wquh, *wkvuh, *woh;
    cudaGetSymbolAddress((void**)&cqh,    g_cqh);
    cudaGetSymbolAddress((void**)&kvh,    g_kvh);
    cudaGetSymbolAddress((void**)&ckvh,   g_ckvh);
    cudaGetSymbolAddress((void**)&qh,     g_qh);
    cudaGetSymbolAddress((void**)&kvuph,  g_kvuph);
    cudaGetSymbolAddress((void**)&attnh,  g_attnh);
    cudaGetSymbolAddress((void**)&xh,     g_xh);
    cudaGetSymbolAddress((void**)&wqkvdh, g_wqkvdh);
    cudaGetSymbolAddress((void**)&wquh,   g_wquh);
    cudaGetSymbolAddress((void**)&wkvuh,  g_wkvuh);
    cudaGetSymbolAddress((void**)&woh,    g_woh);

    cudaFuncSetAttribute(attn_f16_kernel,
                         cudaFuncAttributeMaxDynamicSharedMemorySize,
                         ATT_SMEM_BYTES);
    cudaFuncSetAttribute((void*)gemm_f16_kernel<false, true, false>,
                         cudaFuncAttributeMaxDynamicSharedMemorySize, GEMM_SMEM);
    cudaFuncSetAttribute((void*)gemm_f16_kernel<false, true, true>,
                         cudaFuncAttributeMaxDynamicSharedMemorySize, GEMM_SMEM);
    cudaFuncSetAttribute((void*)gemm_f16_kernel<false, false, false>,
                         cudaFuncAttributeMaxDynamicSharedMemorySize, GEMM_SMEM);
    cudaFuncSetAttribute((void*)gemm_f16_kernel<true, true, false>,
                         cudaFuncAttributeMaxDynamicSharedMemorySize, GEMM_SMEM);

    // One-time resources for the fork/join DAG (deterministic work each call)
    static cudaStream_t s2 = nullptr;
    static cudaEvent_t evFork = nullptr, evW = nullptr, evDown = nullptr,
                       evKV = nullptr;
    if (!s2) {
        cudaStreamCreateWithFlags(&s2, cudaStreamNonBlocking);
        cudaEventCreateWithFlags(&evFork, cudaEventDisableTiming);
        cudaEventCreateWithFlags(&evW,    cudaEventDisableTiming);
        cudaEventCreateWithFlags(&evDown, cudaEventDisableTiming);
        cudaEventCreateWithFlags(&evKV,   cudaEventDisableTiming);
    }

    const float qscale = 0.07216878364870322f;  // 1/sqrt(192)
    const cudaStream_t s0 = 0;

    // ---- fork: side stream converts later-stage weights + rope tables ----
    cudaEventRecord(evFork, s0);
    cudaStreamWaitEvent(s2, evFork, 0);

    rope_tables_kernel<<<(SEQ * 32 + 255) / 256, 256, 0, s2>>>();
    launch_f2h(w_q_up,  wquh,  NH * QKD * QR, qscale, s2);
    launch_f2h(w_kv_up, wkvuh, NH * KVUP_D * KVR, 1.f, s2);
    launch_f2h(w_o,     woh,   DIM * NH * VDIM, 1.f, s2);
    cudaEventRecord(evW, s2);

    // ---- main stream: inputs for down-proj, then down-proj --------------
    launch_f2h(x,         xh,                SEQ * DIM, 1.f, s0);
    launch_f2h(w_q_down,  wqkvdh,            QR * DIM, 1.f, s0);
    launch_f2h(w_kv_down, wqkvdh + QR * DIM, (KVR + ROPE_D) * DIM, 1.f, s0);
    launch_gemm_split_h(xh, wqkvdh, cqh, kvh, SEQ, QR, KVR + ROPE_D, DIM, s0);

    // ---- fork kv branch onto s2 (after down-proj) ------------------------
    cudaEventRecord(evDown, s0);
    cudaStreamWaitEvent(s2, evDown, 0);
    rmsnorm_kernel<<<SEQ, 256, 0, s2>>>(kvh, ckvh, kv_norm_w,
                                        KVR, KVR + ROPE_D, KVR);
    rope_k_kernel<<<(SEQ * 32 + 255) / 256, 256, 0, s2>>>();
    cudaEventRecord(evKV, s2);

    // ---- main stream: q branch -------------------------------------------
    rmsnorm_kernel<<<SEQ, 256, 0, s0>>>(cqh, cqh, q_norm_w, QR, QR, QR);
    cudaStreamWaitEvent(s0, evW, 0);     // wqu + rope tables ready
    launch_gemm_h_rope(cqh, wquh, qh, SEQ, NH * QKD, QR, s0);

    // ---- join kv branch, then kv_up / attention / w_o --------------------
    cudaStreamWaitEvent(s0, evKV, 0);    // ckvh + kropeh ready (wkvuh via evW order)
    launch_gemm_h(ckvh, wkvuh, kvuph, SEQ, NH * KVUP_D, KVR, s0);
    attn_f16_kernel<<<dim3(SEQ / 128, NH), 256, ATT_SMEM_BYTES, s0>>>();
    launch_gemm_f(attnh, woh, out, SEQ, DIM, NH * VDIM, s0);
}